// round 13
// baseline (speedup 1.0000x reference)
#include <cuda_runtime.h>

#define NN 50000
#define EE 640000
#define HCC 128
#define NHH 4
#define NLAY 4
#define NBATCH 64
#define NCLS 88

// ---------------- scratch (static device globals; no allocation) ----------------
__device__ float g_h[NN * HCC];
__device__ float g_hp[NN * HCC];
__device__ float g_asrc[NN * NHH];
__device__ float g_adst[NN * NHH];
__device__ int   g_deg[NN];
__device__ int   g_off[NN + 1];
__device__ int   g_cur[NN];
__device__ int   g_bsum[64];
__device__ int   g_csr_src[EE];
__device__ float g_tcsr[EE];
__device__ uchar2 g_ij[EE];
__device__ float g_sums[NBATCH * HCC];
__device__ float g_cnt[NBATCH];

// piecewise-linear a_edge tables
__device__ int   d_np, d_nn2;
__device__ float d_thrp[HCC], d_thrn[HCC];
__device__ float4 d_PA[(HCC + 1) * NLAY];
__device__ float4 d_PB[(HCC + 1) * NLAY];
__device__ float4 d_SA[(HCC + 1) * NLAY];
__device__ float4 d_SB[(HCC + 1) * NLAY];
__device__ float4 d_CB[NLAY];

// ---------------- zero ----------------
__global__ void k_zero() {
    int i = blockIdx.x * blockDim.x + threadIdx.x;
    if (i < NN) g_deg[i] = 0;
    if (i < NBATCH * HCC) g_sums[i] = 0.f;
    if (i < NBATCH) g_cnt[i] = 0.f;
}

// ---------------- CSR build ----------------
__global__ void k_hist(const int* __restrict__ dst) {
    int i = blockIdx.x * blockDim.x + threadIdx.x;
    if (i < EE) atomicAdd(&g_deg[dst[i]], 1);
}
__global__ void k_scan1() {
    __shared__ int ws[32];
    int t = threadIdx.x;
    int gi = blockIdx.x * 1024 + t;
    int v = (gi < NN) ? g_deg[gi] : 0;
    int lane = t & 31, wid = t >> 5;
    int x = v;
    #pragma unroll
    for (int o = 1; o < 32; o <<= 1) {
        int y = __shfl_up_sync(~0u, x, o);
        if (lane >= o) x += y;
    }
    if (lane == 31) ws[wid] = x;
    __syncthreads();
    if (wid == 0) {
        int y = ws[lane];
        #pragma unroll
        for (int o = 1; o < 32; o <<= 1) {
            int z = __shfl_up_sync(~0u, y, o);
            if (lane >= o) y += z;
        }
        ws[lane] = y;
    }
    __syncthreads();
    int excl = x - v + (wid ? ws[wid - 1] : 0);
    if (gi < NN) g_off[gi] = excl;
    if (t == 1023) g_bsum[blockIdx.x] = excl + v;
}
__global__ void k_scan2() {
    __shared__ int sm2[64];
    int t = threadIdx.x;
    int v = (t < 49) ? g_bsum[t] : 0;
    sm2[t] = v;
    __syncthreads();
    #pragma unroll
    for (int o = 1; o < 64; o <<= 1) {
        int x = (t >= o) ? sm2[t - o] : 0;
        __syncthreads();
        sm2[t] += x;
        __syncthreads();
    }
    if (t < 49) g_bsum[t] = sm2[t] - v;
}
__global__ void k_scan3() {
    int i = blockIdx.x * blockDim.x + threadIdx.x;
    if (i < NN) {
        int o = g_off[i] + g_bsum[i >> 10];
        g_off[i] = o;
        g_cur[i] = o;
    }
    if (i == 0) g_off[NN] = EE;
}
__global__ void k_scatter(const int* __restrict__ src, const int* __restrict__ dst,
                          const float* __restrict__ eattr) {
    int i = blockIdx.x * blockDim.x + threadIdx.x;
    if (i >= EE) return;
    int p = atomicAdd(&g_cur[dst[i]], 1);
    float tv = eattr[i];
    g_csr_src[p] = src[i];
    g_tcsr[p] = tv;
    int np = d_np, nn = d_nn2;
    int lo = 0, hi = np;
    while (lo < hi) { int m = (lo + hi) >> 1; if (d_thrp[m] < tv) lo = m + 1; else hi = m; }
    int ii = lo;
    lo = 0; hi = nn;
    while (lo < hi) { int m = (lo + hi) >> 1; if (d_thrn[m] <= tv) lo = m + 1; else hi = m; }
    g_ij[p] = make_uchar2((unsigned char)ii, (unsigned char)lo);
}

// ---------------- node encoder ----------------
__global__ void k_node_enc(const float* __restrict__ x, const float* __restrict__ W,
                           const float* __restrict__ b, const float* __restrict__ g,
                           const float* __restrict__ be) {
    int t = threadIdx.x;
    int n = blockIdx.x * 8 + (t >> 5);
    if (n >= NN) return;
    int lane = t & 31;
    float4 xv = ((const float4*)x)[n];
    const float4* Wr = (const float4*)W;
    float4 w0 = Wr[lane], w1 = Wr[32 + lane], w2 = Wr[64 + lane], w3 = Wr[96 + lane];
    float4 bv = ((const float4*)b)[lane];
    float4 y;
    y.x = bv.x + xv.x * w0.x + xv.y * w1.x + xv.z * w2.x + xv.w * w3.x;
    y.y = bv.y + xv.x * w0.y + xv.y * w1.y + xv.z * w2.y + xv.w * w3.y;
    y.z = bv.z + xv.x * w0.z + xv.y * w1.z + xv.z * w2.z + xv.w * w3.z;
    y.w = bv.w + xv.x * w0.w + xv.y * w1.w + xv.z * w2.w + xv.w * w3.w;
    float s1 = y.x + y.y + y.z + y.w;
    float s2 = y.x * y.x + y.y * y.y + y.z * y.z + y.w * y.w;
    #pragma unroll
    for (int o = 16; o; o >>= 1) {
        s1 += __shfl_xor_sync(~0u, s1, o);
        s2 += __shfl_xor_sync(~0u, s2, o);
    }
    float mean = s1 * (1.f / HCC);
    float var = s2 * (1.f / HCC) - mean * mean;
    float rstd = rsqrtf(var + 1e-5f);
    float4 gv = ((const float4*)g)[lane];
    float4 bev = ((const float4*)be)[lane];
    float4 r;
    r.x = fmaxf((y.x - mean) * rstd * gv.x + bev.x, 0.f);
    r.y = fmaxf((y.y - mean) * rstd * gv.y + bev.y, 0.f);
    r.z = fmaxf((y.z - mean) * rstd * gv.z + bev.z, 0.f);
    r.w = fmaxf((y.w - mean) * rstd * gv.w + bev.w, 0.f);
    ((float4*)g_h)[n * 32 + lane] = r;
}

// ---------------- piecewise a_edge tables (1 block, 128 threads) ----------------
__global__ void k_prep(const float* __restrict__ We, const float* __restrict__ atte,
                       const float* __restrict__ Wee, const float* __restrict__ bee) {
    __shared__ float stau[HCC], sw_[HCC], sb_[HCC];
    __shared__ int sflag[HCC];
    __shared__ float swm[NLAY * NHH][HCC];
    __shared__ float sbm[NLAY * NHH][HCC];
    __shared__ int srtp[HCC], srtn[HCC];
    __shared__ int s_np, s_nn;
    int k = threadIdx.x;
    if (k == 0) { s_np = 0; s_nn = 0; }
    float w = Wee[k], b = bee[k];
    #pragma unroll
    for (int l = 0; l < NLAY; l++) {
        #pragma unroll
        for (int h = 0; h < NHH; h++) {
            float m = 0.f;
            #pragma unroll 8
            for (int c = 0; c < 32; c++)
                m += We[l * HCC * HCC + k * HCC + h * 32 + c] * atte[l * HCC + h * 32 + c];
            swm[l * NHH + h][k] = w * m;
            sbm[l * NHH + h][k] = b * m;
        }
    }
    sw_[k] = w; sb_[k] = b;
    int flag = (w > 0.f) ? 0 : ((w < 0.f) ? 1 : 2);
    sflag[k] = flag;
    stau[k] = (flag < 2) ? (-b / w) : 0.f;
    __syncthreads();
    float tk = stau[k];
    int rank = 0, cnt = 0;
    if (flag < 2) {
        for (int j = 0; j < HCC; j++)
            if (sflag[j] == flag) {
                cnt++;
                if (stau[j] < tk || (stau[j] == tk && j < k)) rank++;
            }
    }
    if (flag == 0 && rank == 0) s_np = cnt;
    if (flag == 1 && rank == 0) s_nn = cnt;
    if (flag == 0) { srtp[rank] = k; d_thrp[rank] = tk; }
    if (flag == 1) { srtn[rank] = k; d_thrn[rank] = tk; }
    __syncthreads();
    int np = s_np, nn = s_nn;
    float* PAf = (float*)d_PA; float* PBf = (float*)d_PB;
    float* SAf = (float*)d_SA; float* SBf = (float*)d_SB;
    float* CBf = (float*)d_CB;
    if (k < 16) {
        int c = k, l = k >> 2, h = k & 3;
        float ra = 0.f, rb = 0.f;
        PAf[(0 * NLAY + l) * 4 + h] = 0.f;
        PBf[(0 * NLAY + l) * 4 + h] = 0.f;
        for (int i = 0; i < np; i++) {
            int kk = srtp[i];
            ra += swm[c][kk]; rb += sbm[c][kk];
            PAf[((i + 1) * NLAY + l) * 4 + h] = ra;
            PBf[((i + 1) * NLAY + l) * 4 + h] = rb;
        }
    } else if (k < 32) {
        int c = k - 16, l = c >> 2, h = c & 3;
        float ra = 0.f, rb = 0.f;
        SAf[(nn * NLAY + l) * 4 + h] = 0.f;
        SBf[(nn * NLAY + l) * 4 + h] = 0.f;
        for (int i = nn - 1; i >= 0; i--) {
            int kk = srtn[i];
            ra += swm[c][kk]; rb += sbm[c][kk];
            SAf[(i * NLAY + l) * 4 + h] = ra;
            SBf[(i * NLAY + l) * 4 + h] = rb;
        }
    } else if (k < 48) {
        int c = k - 32;
        float r = 0.f;
        for (int j = 0; j < HCC; j++)
            if (sflag[j] == 2 && sb_[j] > 0.f) r += sbm[c][j];
        CBf[c] = r;
    }
    if (k == 0) { d_np = np; d_nn2 = nn; }
}

// ---- GEMM: 128x128 tile, 8x8 micro-tile, fused a_src/a_dst epilogue ----
#define GM 128
__global__ __launch_bounds__(256, 2) void k_gemm(const float* __restrict__ W,
                                                 const float* __restrict__ atts,
                                                 const float* __restrict__ attd) {
    extern __shared__ float smem[];
    float* Ws = smem;               // [128][128]
    float* Xs = smem + HCC * HCC;   // [64][128] k-major transposed chunk
    int t = threadIdx.x;
    int tx = t & 15, ty = t >> 4;
    const float4* W4 = (const float4*)W;
    float4* Ws4 = (float4*)Ws;
    #pragma unroll
    for (int i = 0; i < 16; i++) Ws4[t + 256 * i] = W4[t + 256 * i];
    // att vectors for this thread's 8 cols (lo: cols tx*4..+3, hi: 64+tx*4..+3)
    float4 asl = ((const float4*)atts)[tx], ash = ((const float4*)atts)[16 + tx];
    float4 adl = ((const float4*)attd)[tx], adh_ = ((const float4*)attd)[16 + tx];

    int nt = (NN + GM - 1) / GM;
    for (int tile = blockIdx.x; tile < nt; tile += gridDim.x) {
        int base = tile * GM;
        float acc[8][8];
        #pragma unroll
        for (int i = 0; i < 8; i++)
            #pragma unroll
            for (int j = 0; j < 8; j++) acc[i][j] = 0.f;
        #pragma unroll
        for (int kc = 0; kc < 2; kc++) {
            __syncthreads();
            int r = t >> 1;
            int gr = base + r;
            #pragma unroll
            for (int i = 0; i < 8; i++) {
                int fc = (t & 1) * 8 + i;
                float4 v = (gr < NN) ? ((const float4*)g_h)[gr * 32 + kc * 16 + fc]
                                     : make_float4(0.f, 0.f, 0.f, 0.f);
                int kl = fc * 4;
                Xs[(kl + 0) * GM + r] = v.x;
                Xs[(kl + 1) * GM + r] = v.y;
                Xs[(kl + 2) * GM + r] = v.z;
                Xs[(kl + 3) * GM + r] = v.w;
            }
            __syncthreads();
            #pragma unroll 4
            for (int k = 0; k < 64; k++) {
                float4 a0 = *(const float4*)&Xs[k * GM + ty * 4];
                float4 a1 = *(const float4*)&Xs[k * GM + 64 + ty * 4];
                float4 b0 = *(const float4*)&Ws[(kc * 64 + k) * HCC + tx * 4];
                float4 b1 = *(const float4*)&Ws[(kc * 64 + k) * HCC + 64 + tx * 4];
                float ar[8] = {a0.x, a0.y, a0.z, a0.w, a1.x, a1.y, a1.z, a1.w};
                float bc[8] = {b0.x, b0.y, b0.z, b0.w, b1.x, b1.y, b1.z, b1.w};
                #pragma unroll
                for (int i = 0; i < 8; i++)
                    #pragma unroll
                    for (int j = 0; j < 8; j++)
                        acc[i][j] += ar[i] * bc[j];
            }
        }
        #pragma unroll
        for (int i = 0; i < 8; i++) {
            int r = base + ((i < 4) ? (ty * 4 + i) : (64 + ty * 4 + i - 4));
            // per-head partial dots: lo cols belong to head tx>>3, hi cols to head 2+(tx>>3)
            float vsl = acc[i][0] * asl.x + acc[i][1] * asl.y + acc[i][2] * asl.z + acc[i][3] * asl.w;
            float vsh = acc[i][4] * ash.x + acc[i][5] * ash.y + acc[i][6] * ash.z + acc[i][7] * ash.w;
            float vdl = acc[i][0] * adl.x + acc[i][1] * adl.y + acc[i][2] * adl.z + acc[i][3] * adl.w;
            float vdh = acc[i][4] * adh_.x + acc[i][5] * adh_.y + acc[i][6] * adh_.z + acc[i][7] * adh_.w;
            #pragma unroll
            for (int o = 1; o < 8; o <<= 1) {
                vsl += __shfl_xor_sync(~0u, vsl, o);
                vsh += __shfl_xor_sync(~0u, vsh, o);
                vdl += __shfl_xor_sync(~0u, vdl, o);
                vdh += __shfl_xor_sync(~0u, vdh, o);
            }
            if (r < NN) {
                *(float4*)&g_hp[r * HCC + tx * 4]      = make_float4(acc[i][0], acc[i][1], acc[i][2], acc[i][3]);
                *(float4*)&g_hp[r * HCC + 64 + tx * 4] = make_float4(acc[i][4], acc[i][5], acc[i][6], acc[i][7]);
                if ((tx & 7) == 0) {
                    int h0 = tx >> 3;
                    g_asrc[r * NHH + h0]     = vsl;
                    g_asrc[r * NHH + 2 + h0] = vsh;
                    g_adst[r * NHH + h0]     = vdl;
                    g_adst[r * NHH + 2 + h0] = vdh;
                }
            }
        }
    }
}

// ---- single-pass softmax-aggregate, lane-parallel edge metadata ----
// NOTE: all 4 head weights must be broadcast and the head selected on the
// RECEIVER (lane) side — selecting before the shuffle uses the source lane's
// head and is wrong (R11 bug).
__global__ void k_agg(const float* __restrict__ bias, const float* __restrict__ gam,
                      const float* __restrict__ bet, int layer) {
    int t = threadIdx.x;
    int n = blockIdx.x * 8 + (t >> 5);
    if (n >= NN) return;
    int lane = t & 31;
    int hh = lane >> 3;
    int o0 = g_off[n];
    int deg = g_off[n + 1] - o0;
    float4 adn = *(const float4*)&g_adst[n * NHH];
    float4 CB = d_CB[layer];
    const float4* hp4 = (const float4*)g_hp;

    float4 acc = make_float4(0.f, 0.f, 0.f, 0.f);
    float dn0 = 0.f, dn1 = 0.f, dn2 = 0.f, dn3 = 0.f;
    for (int b0 = 0; b0 < deg; b0 += 32) {
        int jj = b0 + lane;
        bool val = jj < deg;
        int p = o0 + (val ? jj : (deg - 1));
        int sv = g_csr_src[p];
        float tv = g_tcsr[p];
        uchar2 ij = g_ij[p];
        float4 as = *(const float4*)&g_asrc[sv * NHH];
        float4 A = d_PA[ij.x * NLAY + layer];
        float4 B = d_PB[ij.x * NLAY + layer];
        float4 A2 = d_SA[ij.y * NLAY + layer];
        float4 B2 = d_SB[ij.y * NLAY + layer];
        float a0 = as.x + adn.x + tv * (A.x + A2.x) + B.x + B2.x + CB.x; a0 = a0 >= 0.f ? a0 : 0.2f * a0;
        float a1 = as.y + adn.y + tv * (A.y + A2.y) + B.y + B2.y + CB.y; a1 = a1 >= 0.f ? a1 : 0.2f * a1;
        float a2 = as.z + adn.z + tv * (A.z + A2.z) + B.z + B2.z + CB.z; a2 = a2 >= 0.f ? a2 : 0.2f * a2;
        float a3 = as.w + adn.w + tv * (A.w + A2.w) + B.w + B2.w + CB.w; a3 = a3 >= 0.f ? a3 : 0.2f * a3;
        float e0 = val ? __expf(a0) : 0.f;
        float e1 = val ? __expf(a1) : 0.f;
        float e2 = val ? __expf(a2) : 0.f;
        float e3 = val ? __expf(a3) : 0.f;
        dn0 += e0; dn1 += e1; dn2 += e2; dn3 += e3;
        int cnt = deg - b0; if (cnt > 32) cnt = 32;
        for (int q = 0; q < cnt; q++) {
            int s = __shfl_sync(~0u, sv, q);
            float w0 = __shfl_sync(~0u, e0, q);
            float w1 = __shfl_sync(~0u, e1, q);
            float w2 = __shfl_sync(~0u, e2, q);
            float w3 = __shfl_sync(~0u, e3, q);
            float w = (hh & 2) ? ((hh & 1) ? w3 : w2) : ((hh & 1) ? w1 : w0);
            float4 hp = hp4[s * 32 + lane];
            acc.x += w * hp.x; acc.y += w * hp.y; acc.z += w * hp.z; acc.w += w * hp.w;
        }
    }
    #pragma unroll
    for (int o = 16; o; o >>= 1) {
        dn0 += __shfl_xor_sync(~0u, dn0, o);
        dn1 += __shfl_xor_sync(~0u, dn1, o);
        dn2 += __shfl_xor_sync(~0u, dn2, o);
        dn3 += __shfl_xor_sync(~0u, dn3, o);
    }
    float den = (hh & 2) ? ((hh & 1) ? dn3 : dn2) : ((hh & 1) ? dn1 : dn0);
    float rden = den > 0.f ? 1.f / den : 0.f;

    float4 bv = ((const float4*)bias)[lane];
    float4 v = make_float4(acc.x * rden + bv.x, acc.y * rden + bv.y,
                           acc.z * rden + bv.z, acc.w * rden + bv.w);
    float s1 = v.x + v.y + v.z + v.w;
    float s2 = v.x * v.x + v.y * v.y + v.z * v.z + v.w * v.w;
    #pragma unroll
    for (int o = 16; o; o >>= 1) {
        s1 += __shfl_xor_sync(~0u, s1, o);
        s2 += __shfl_xor_sync(~0u, s2, o);
    }
    float mean = s1 * (1.f / HCC);
    float var = s2 * (1.f / HCC) - mean * mean;
    float rstd = rsqrtf(var + 1e-5f);
    float4 gv = ((const float4*)gam)[lane];
    float4 bev = ((const float4*)bet)[lane];
    float4 hold = ((const float4*)g_h)[n * 32 + lane];
    float4 r;
    r.x = hold.x + fmaxf((v.x - mean) * rstd * gv.x + bev.x, 0.f);
    r.y = hold.y + fmaxf((v.y - mean) * rstd * gv.y + bev.y, 0.f);
    r.z = hold.z + fmaxf((v.z - mean) * rstd * gv.z + bev.z, 0.f);
    r.w = hold.w + fmaxf((v.w - mean) * rstd * gv.w + bev.w, 0.f);
    ((float4*)g_h)[n * 32 + lane] = r;
}

// ---------------- pooling + classifier ----------------
__global__ void k_count(const int* __restrict__ batch) {
    int i = blockIdx.x * blockDim.x + threadIdx.x;
    if (i < NN) atomicAdd(&g_cnt[batch[i]], 1.f);
}
__global__ void k_pool(const int* __restrict__ batch) {
    int n0 = blockIdx.x * 256;
    int n1 = n0 + 256; if (n1 > NN) n1 = NN;
    int c = threadIdx.x;
    float run = 0.f;
    int curb = batch[n0];
    for (int n = n0; n < n1; n++) {
        int b = batch[n];
        if (b != curb) {
            atomicAdd(&g_sums[curb * HCC + c], run);
            run = 0.f; curb = b;
        }
        run += g_h[n * HCC + c];
    }
    atomicAdd(&g_sums[curb * HCC + c], run);
}
__global__ void k_cls(const float* __restrict__ W1, const float* __restrict__ b1,
                      const float* __restrict__ W2, const float* __restrict__ b2,
                      float* __restrict__ out) {
    __shared__ float sp[HCC];
    __shared__ float sz[64];
    int b = blockIdx.x;
    int c = threadIdx.x;
    float cnt = fmaxf(g_cnt[b], 1.f);
    sp[c] = g_sums[b * HCC + c] / cnt;
    __syncthreads();
    if (c < 64) {
        float a = b1[c];
        #pragma unroll 4
        for (int k = 0; k < HCC; k++) a += sp[k] * W1[k * 64 + c];
        sz[c] = fmaxf(a, 0.f);
    }
    __syncthreads();
    if (c < NCLS) {
        float a = b2[c];
        #pragma unroll 4
        for (int k = 0; k < 64; k++) a += sz[k] * W2[k * NCLS + c];
        out[b * NCLS + c] = a;
    }
}

// ---------------- launch ----------------
extern "C" void kernel_launch(void* const* d_in, const int* in_sizes, int n_in,
                              void* d_out, int out_size) {
    (void)in_sizes; (void)n_in; (void)out_size;
    const float* x     = (const float*)d_in[0];
    const float* eattr = (const float*)d_in[1];
    const int*   eidx  = (const int*)d_in[2];
    const int*   batch = (const int*)d_in[3];
    const float* W_ne  = (const float*)d_in[4];
    const float* b_ne  = (const float*)d_in[5];
    const float* g_ne  = (const float*)d_in[6];
    const float* be_ne = (const float*)d_in[7];
    const float* W_ee  = (const float*)d_in[8];
    const float* b_ee  = (const float*)d_in[9];
    const float* Wl    = (const float*)d_in[10];
    const float* att_s = (const float*)d_in[11];
    const float* att_d = (const float*)d_in[12];
    const float* We    = (const float*)d_in[13];
    const float* att_e = (const float*)d_in[14];
    const float* b_l   = (const float*)d_in[15];
    const float* g_l   = (const float*)d_in[16];
    const float* be_l  = (const float*)d_in[17];
    const float* W1    = (const float*)d_in[18];
    const float* b1    = (const float*)d_in[19];
    const float* W2    = (const float*)d_in[20];
    const float* b2    = (const float*)d_in[21];
    float* out = (float*)d_out;

    const int* src = eidx;
    const int* dst = eidx + EE;

    const int SMEM_GEMM = (HCC * HCC + 64 * GM) * 4;   // 96 KB
    cudaFuncSetAttribute(k_gemm, cudaFuncAttributeMaxDynamicSharedMemorySize, SMEM_GEMM);

    // tables first (k_scatter needs thresholds)
    k_prep<<<1, HCC>>>(We, att_e, W_ee, b_ee);

    // CSR build + zero
    k_zero<<<(NN + 255) / 256, 256>>>();
    k_hist<<<(EE + 255) / 256, 256>>>(dst);
    k_scan1<<<49, 1024>>>();
    k_scan2<<<1, 64>>>();
    k_scan3<<<(NN + 255) / 256, 256>>>();
    k_scatter<<<(EE + 255) / 256, 256>>>(src, dst, eattr);

    // node encoder
    k_node_enc<<<(NN + 7) / 8, 256>>>(x, W_ne, b_ne, g_ne, be_ne);

    for (int l = 0; l < NLAY; l++) {
        k_gemm<<<296, 256, SMEM_GEMM>>>(Wl + l * HCC * HCC, att_s + l * HCC, att_d + l * HCC);
        k_agg<<<(NN + 7) / 8, 256>>>(b_l + l * HCC, g_l + l * HCC, be_l + l * HCC, l);
    }

    // pooling + classifier
    k_count<<<(NN + 255) / 256, 256>>>(batch);
    k_pool<<<(NN + 255) / 256, HCC>>>(batch);
    k_cls<<<NBATCH, HCC>>>(W1, b1, W2, b2, out);
}